// round 10
// baseline (speedup 1.0000x reference)
#include <cuda_runtime.h>
#include <cuda_bf16.h>
#include <math.h>

#define N_  256
#define T_  128
#define D_  512
#define H_  1024
#define C4_ 4096
#define KT_ 2560            // H (h) + H (attn) + D (x)
#define KC  32
#define NTILES (KT_/KC)     // 80
#define STAGES 4
#define SA 40               // smem row stride in halves (80B, conflict-free for ldmatrix)
#define SB 40
#define STAGE_BYTES (2*(64*SA*2) + 2*(128*SB*2))   // 30720 B per stage
#define CS 132              // epilogue Cs stride (floats)

// ---- device scratch (no runtime allocation allowed) ----
__device__ __align__(16) __nv_bfloat16 g_Wh[(size_t)C4_ * KT_]; // weight hi, [col][k]
__device__ __align__(16) __nv_bfloat16 g_Wl[(size_t)C4_ * KT_]; // weight lo
__device__ __align__(16) __nv_bfloat16 g_xh[(size_t)N_ * T_ * D_];
__device__ __align__(16) __nv_bfloat16 g_xl[(size_t)N_ * T_ * D_];
__device__ __align__(16) float         g_bv[C4_];
__device__ __align__(16) float         g_h[2][N_ * H_];
__device__ __align__(16) __nv_bfloat16 g_zh[2][N_ * H_];  // h hi (ping-pong)
__device__ __align__(16) __nv_bfloat16 g_zl[2][N_ * H_];  // h lo
__device__ __align__(16) __nv_bfloat16 g_ah[N_ * H_];     // attn hi
__device__ __align__(16) __nv_bfloat16 g_al[N_ * H_];     // attn lo
__device__ __align__(16) float         g_c[N_ * H_];

__device__ __forceinline__ float sigf(float x) { return 1.0f / (1.0f + expf(-x)); }

__device__ __forceinline__ void split2(float v, __nv_bfloat16& hi, __nv_bfloat16& lo) {
    hi = __float2bfloat16(v);
    lo = __float2bfloat16(v - __bfloat162float(hi));
}

__device__ __forceinline__ void mma_bf16(float c[4], const unsigned int a[4], const unsigned int b[2]) {
    asm volatile(
        "mma.sync.aligned.m16n8k16.row.col.f32.bf16.bf16.f32 "
        "{%0,%1,%2,%3},{%4,%5,%6,%7},{%8,%9},{%0,%1,%2,%3};"
        : "+f"(c[0]), "+f"(c[1]), "+f"(c[2]), "+f"(c[3])
        : "r"(a[0]), "r"(a[1]), "r"(a[2]), "r"(a[3]), "r"(b[0]), "r"(b[1]));
}

__device__ __forceinline__ void ldsm_x4(unsigned int a[4], unsigned int addr) {
    asm volatile("ldmatrix.sync.aligned.m8n8.x4.shared.b16 {%0,%1,%2,%3}, [%4];"
                 : "=r"(a[0]), "=r"(a[1]), "=r"(a[2]), "=r"(a[3]) : "r"(addr));
}
__device__ __forceinline__ void ldsm_x2(unsigned int b[2], unsigned int addr) {
    asm volatile("ldmatrix.sync.aligned.m8n8.x2.shared.b16 {%0,%1}, [%2];"
                 : "=r"(b[0]), "=r"(b[1]) : "r"(addr));
}
__device__ __forceinline__ void cpa16(unsigned int dst, const void* src) {
    asm volatile("cp.async.cg.shared.global [%0], [%1], 16;" :: "r"(dst), "l"(src));
}

// ---- one-time prep kernels ----
// g_Wh/g_Wl[c][k]: col c' = j*4+q <-> original col q*H+j; k rows: [0,H)=Wh, [H,2H)=Wattn, [2H,..)=Wx
__global__ void reorder_kernel(const float* __restrict__ Wx, const float* __restrict__ Wh,
                               const float* __restrict__ Wattn, const float* __restrict__ b) {
    int k = blockIdx.x * blockDim.x + threadIdx.x;
    int c = blockIdx.y;
    if (k >= KT_) return;
    int oc = (c & 3) * H_ + (c >> 2);
    float w;
    if (k < H_)            w = Wh[k * C4_ + oc];
    else if (k < 2 * H_)   w = Wattn[(k - H_) * C4_ + oc];
    else                   w = Wx[(k - 2 * H_) * C4_ + oc];
    __nv_bfloat16 hi, lo;
    split2(w, hi, lo);
    g_Wh[(size_t)c * KT_ + k] = hi;
    g_Wl[(size_t)c * KT_ + k] = lo;
    if (k == 0 && blockIdx.x == 0) g_bv[c] = b[oc];
}

__global__ void xsplit_kernel(const float* __restrict__ x) {
    size_t i = (size_t)blockIdx.x * blockDim.x + threadIdx.x;
    size_t total = (size_t)N_ * T_ * D_;
    size_t stride = (size_t)gridDim.x * blockDim.x;
    for (; i < total; i += stride) {
        __nv_bfloat16 hi, lo;
        split2(x[i], hi, lo);
        g_xh[i] = hi;
        g_xl[i] = lo;
    }
}

__global__ void init_kernel(const float* __restrict__ A) {
    int i = blockIdx.x * blockDim.x + threadIdx.x;
    if (i < N_ * H_) {
        const float4* a = reinterpret_cast<const float4*>(A + (size_t)i * 16);
        float4 a0 = a[0], a1 = a[1], a2 = a[2], a3 = a[3];
        float s = a0.x + a0.y + a0.z + a0.w + a1.x + a1.y + a1.z + a1.w
                + a2.x + a2.y + a2.z + a2.w + a3.x + a3.y + a3.z + a3.w;
        s *= (1.0f / 16.0f);
        g_h[0][i] = s;
        g_c[i] = s;
        __nv_bfloat16 hi, lo;
        split2(s, hi, lo);
        g_zh[0][i] = hi;
        g_zl[0][i] = lo;
    }
}

// ---- per-step attention (single pass, A rows in regs, 512 threads) ----
__global__ __launch_bounds__(512) void attn_kernel(const float* __restrict__ A, int cur) {
    int n = blockIdx.x;
    int tid = threadIdx.x;
    const float* __restrict__ hn = g_h[cur] + n * H_;
    const float* __restrict__ An = A + (size_t)n * H_ * 16;

    float4 ar[2][4];
    float s[16];
#pragma unroll
    for (int l = 0; l < 16; l++) s[l] = 0.0f;
#pragma unroll
    for (int r = 0; r < 2; r++) {
        int hh = tid + r * 512;
        float hv = hn[hh];
        const float4* ap = reinterpret_cast<const float4*>(An + hh * 16);
#pragma unroll
        for (int v = 0; v < 4; v++) {
            float4 a = ap[v];
            ar[r][v] = a;
            s[v * 4 + 0] += a.x * hv;
            s[v * 4 + 1] += a.y * hv;
            s[v * 4 + 2] += a.z * hv;
            s[v * 4 + 3] += a.w * hv;
        }
    }
#pragma unroll
    for (int off = 16; off > 0; off >>= 1)
#pragma unroll
        for (int l = 0; l < 16; l++) s[l] += __shfl_xor_sync(0xffffffffu, s[l], off);

    __shared__ float red[16][16];
    int wid = tid >> 5, lane = tid & 31;
    if (lane == 0)
#pragma unroll
        for (int l = 0; l < 16; l++) red[wid][l] = s[l];
    __syncthreads();

    float w[16];
    float mx = -1e30f;
#pragma unroll
    for (int l = 0; l < 16; l++) {
        float t = 0.0f;
#pragma unroll
        for (int ww = 0; ww < 16; ww++) t += red[ww][l];
        w[l] = t * 0.03125f;   // 1/sqrt(1024)
        mx = fmaxf(mx, w[l]);
    }
    float sum = 0.0f;
#pragma unroll
    for (int l = 0; l < 16; l++) { w[l] = expf(w[l] - mx); sum += w[l]; }
    float inv = 1.0f / sum;
#pragma unroll
    for (int l = 0; l < 16; l++) w[l] *= inv;

#pragma unroll
    for (int r = 0; r < 2; r++) {
        int hh = tid + r * 512;
        float acc = 0.0f;
#pragma unroll
        for (int v = 0; v < 4; v++) {
            float4 a = ar[r][v];
            acc += a.x * w[v * 4 + 0] + a.y * w[v * 4 + 1]
                 + a.z * w[v * 4 + 2] + a.w * w[v * 4 + 3];
        }
        __nv_bfloat16 hi, lo;
        split2(acc, hi, lo);
        g_ah[n * H_ + hh] = hi;
        g_al[n * H_ + hh] = lo;
    }
}

// ---- fused step: [h|attn|x_t] @ W (bf16-split mma.sync, cp.async 4-stage, ldmatrix) + LSTM ----
__global__ __launch_bounds__(256) void step_kernel(float* __restrict__ out, int t, int cur) {
    extern __shared__ __align__(16) unsigned char sm[];
    const unsigned int smb = (unsigned int)__cvta_generic_to_shared(sm);

    const int tid = threadIdx.x;
    const int bn = blockIdx.x * 128;   // gate-interleaved column base
    const int bm = blockIdx.y * 64;    // batch-row base
    const int nxt = cur ^ 1;

    const int wid = tid >> 5, lane = tid & 31;
    const int wm = wid >> 2, wn = wid & 3;        // 2 x 4 warp grid
    const int cprow = tid >> 2, cpq = tid & 3;    // cp.async mapping

    float acc[2][4][4];
#pragma unroll
    for (int mt = 0; mt < 2; mt++)
#pragma unroll
        for (int nt = 0; nt < 4; nt++)
#pragma unroll
            for (int q = 0; q < 4; q++) acc[mt][nt][q] = 0.0f;

    const __nv_bfloat16* zh = g_zh[cur];
    const __nv_bfloat16* zl = g_zl[cur];

    // ---- stage issue helper (inlined via lambda) ----
    auto issue = [&](int tl) {
        int k0 = tl * KC;
        unsigned int base = smb + (tl % STAGES) * STAGE_BYTES;
        // A tile: 64 rows x 32 halves (hi + lo)
        int n = bm + cprow;
        const __nv_bfloat16 *sh, *sl;
        if (k0 < H_) {
            sh = zh + n * H_ + k0;  sl = zl + n * H_ + k0;
        } else if (k0 < 2 * H_) {
            sh = g_ah + n * H_ + (k0 - H_);  sl = g_al + n * H_ + (k0 - H_);
        } else {
            size_t o = ((size_t)n * T_ + t) * D_ + (k0 - 2 * H_);
            sh = g_xh + o;  sl = g_xl + o;
        }
        cpa16(base + cprow * (SA * 2) + cpq * 16, sh + cpq * 8);
        cpa16(base + 64 * SA * 2 + cprow * (SA * 2) + cpq * 16, sl + cpq * 8);
        // B tile: 128 cols x 32 halves (hi + lo)
#pragma unroll
        for (int i = 0; i < 2; i++) {
            int cl = i * 64 + cprow;
            const __nv_bfloat16* wsrc_h = g_Wh + (size_t)(bn + cl) * KT_ + k0 + cpq * 8;
            const __nv_bfloat16* wsrc_l = g_Wl + (size_t)(bn + cl) * KT_ + k0 + cpq * 8;
            cpa16(base + 2 * 64 * SA * 2 + cl * (SB * 2) + cpq * 16, wsrc_h);
            cpa16(base + 2 * 64 * SA * 2 + 128 * SB * 2 + cl * (SB * 2) + cpq * 16, wsrc_l);
        }
    };

    // prologue: fill STAGES-1 stages
#pragma unroll
    for (int s = 0; s < STAGES - 1; s++) {
        issue(s);
        asm volatile("cp.async.commit_group;");
    }

    // ldmatrix per-lane address components (byte offsets within stage)
    const int a_row_l = (lane & 15);
    const int a_k_l = (lane >> 4) << 3;
    const int b_col_l = (lane & 7);
    const int b_k_l = (lane & 8) ? 8 : 0;

    for (int tile = 0; tile < NTILES; tile++) {
        asm volatile("cp.async.wait_group %0;" :: "n"(STAGES - 2));
        __syncthreads();
        int pf = tile + STAGES - 1;
        if (pf < NTILES) issue(pf);
        asm volatile("cp.async.commit_group;");

        unsigned int base = smb + (tile % STAGES) * STAGE_BYTES;
        unsigned int baseAh = base;
        unsigned int baseAl = base + 64 * SA * 2;
        unsigned int baseBh = base + 2 * 64 * SA * 2;
        unsigned int baseBl = baseBh + 128 * SB * 2;

#pragma unroll
        for (int kb = 0; kb < KC; kb += 16) {
            unsigned int ah[2][4], al[2][4], bh[4][2], bl[4][2];
#pragma unroll
            for (int mt = 0; mt < 2; mt++) {
                int row = wm * 32 + mt * 16 + a_row_l;
                int kk = kb + a_k_l;
                ldsm_x4(ah[mt], baseAh + (row * SA + kk) * 2);
                ldsm_x4(al[mt], baseAl + (row * SA + kk) * 2);
            }
#pragma unroll
            for (int nt = 0; nt < 4; nt++) {
                int col = wn * 32 + nt * 8 + b_col_l;
                int kk = kb + b_k_l;
                ldsm_x2(bh[nt], baseBh + (col * SB + kk) * 2);
                ldsm_x2(bl[nt], baseBl + (col * SB + kk) * 2);
            }
            // 3 passes, dependency reuse distance = 8
#pragma unroll
            for (int mt = 0; mt < 2; mt++)
#pragma unroll
                for (int nt = 0; nt < 4; nt++)
                    mma_bf16(acc[mt][nt], ah[mt], bh[nt]);
#pragma unroll
            for (int mt = 0; mt < 2; mt++)
#pragma unroll
                for (int nt = 0; nt < 4; nt++)
                    mma_bf16(acc[mt][nt], ah[mt], bl[nt]);
#pragma unroll
            for (int mt = 0; mt < 2; mt++)
#pragma unroll
                for (int nt = 0; nt < 4; nt++)
                    mma_bf16(acc[mt][nt], al[mt], bh[nt]);
        }
    }

    // ---- epilogue: regroup gates via smem, fused LSTM pointwise ----
    asm volatile("cp.async.wait_group 0;");
    __syncthreads();
    float* Cs = (float*)sm;
    const int g = lane >> 2, tg = lane & 3;
#pragma unroll
    for (int mt = 0; mt < 2; mt++)
#pragma unroll
        for (int nt = 0; nt < 4; nt++) {
            int r0 = wm * 32 + mt * 16 + g;
            int col = wn * 32 + nt * 8 + tg * 2;
            Cs[r0 * CS + col]           = acc[mt][nt][0];
            Cs[r0 * CS + col + 1]       = acc[mt][nt][1];
            Cs[(r0 + 8) * CS + col]     = acc[mt][nt][2];
            Cs[(r0 + 8) * CS + col + 1] = acc[mt][nt][3];
        }
    __syncthreads();

#pragma unroll
    for (int i = 0; i < 8; i++) {
        int lin = tid + i * 256;
        int m = lin >> 5, jj = lin & 31;
        float4 gg = *(const float4*)&Cs[m * CS + jj * 4];
        float4 bb = *(const float4*)&g_bv[bn + jj * 4];
        int n = bm + m;
        int j = (bn >> 2) + jj;
        float gi = gg.x + bb.x;
        float gf = gg.y + bb.y;
        float go = gg.z + bb.z;
        float gq = gg.w + bb.w;
        float cold = g_c[n * H_ + j];
        float cn = sigf(gf) * cold + sigf(gi) * tanhf(gq);
        float hn = sigf(go) * tanhf(cn);
        g_c[n * H_ + j] = cn;
        g_h[nxt][n * H_ + j] = hn;
        __nv_bfloat16 hi, lo;
        split2(hn, hi, lo);
        g_zh[nxt][n * H_ + j] = hi;
        g_zl[nxt][n * H_ + j] = lo;
        out[((size_t)n * T_ + t) * H_ + j] = hn;
    }
}

extern "C" void kernel_launch(void* const* d_in, const int* in_sizes, int n_in,
                              void* d_out, int out_size) {
    (void)in_sizes; (void)n_in; (void)out_size;
    const float* x     = (const float*)d_in[0];
    const float* A     = (const float*)d_in[1];
    const float* Wx    = (const float*)d_in[2];
    const float* Wh    = (const float*)d_in[3];
    const float* Wattn = (const float*)d_in[4];
    const float* b     = (const float*)d_in[5];
    float* out = (float*)d_out;

    cudaFuncSetAttribute(step_kernel, cudaFuncAttributeMaxDynamicSharedMemorySize,
                         STAGES * STAGE_BYTES);

    reorder_kernel<<<dim3(KT_ / 256, C4_), 256>>>(Wx, Wh, Wattn, b);
    xsplit_kernel<<<2048, 256>>>(x);
    init_kernel<<<(N_ * H_ + 255) / 256, 256>>>(A);

    int cur = 0;
    for (int t = 0; t < T_; t++) {
        attn_kernel<<<N_, 512>>>(A, cur);
        step_kernel<<<dim3(C4_ / 128, N_ / 64), 256, STAGES * STAGE_BYTES>>>(out, t, cur);
        cur ^= 1;
    }
}

// round 11
// speedup vs baseline: 1.0014x; 1.0014x over previous
#include <cuda_runtime.h>
#include <cuda_bf16.h>
#include <math.h>

#define N_  256
#define T_  128
#define D_  512
#define H_  1024
#define C4_ 4096
#define KT_ 2560            // H (h) + H (attn) + D (x)
#define KC  32
#define NTILES (KT_/KC)     // 80
#define STAGES 4
#define SA 40               // smem row stride in halves (80B, conflict-free for ldmatrix)
#define SB 40
#define STAGE_BYTES (2*(64*SA*2) + 2*(128*SB*2))   // 30720 B per stage
#define CS 132              // epilogue Cs stride (floats)

// ---- device scratch (no runtime allocation allowed) ----
__device__ __align__(16) __nv_bfloat16 g_Wh[(size_t)C4_ * KT_]; // weight hi, [col][k]
__device__ __align__(16) __nv_bfloat16 g_Wl[(size_t)C4_ * KT_]; // weight lo
__device__ __align__(16) __nv_bfloat16 g_xh[(size_t)N_ * T_ * D_];
__device__ __align__(16) __nv_bfloat16 g_xl[(size_t)N_ * T_ * D_];
__device__ __align__(16) float         g_bv[C4_];
__device__ __align__(16) float         g_h[2][N_ * H_];
__device__ __align__(16) __nv_bfloat16 g_zh[2][N_ * H_];  // h hi (ping-pong)
__device__ __align__(16) __nv_bfloat16 g_zl[2][N_ * H_];  // h lo
__device__ __align__(16) __nv_bfloat16 g_ah[N_ * H_];     // attn hi
__device__ __align__(16) __nv_bfloat16 g_al[N_ * H_];     // attn lo
__device__ __align__(16) float         g_c[N_ * H_];

__device__ __forceinline__ float sigf(float x) { return 1.0f / (1.0f + expf(-x)); }

__device__ __forceinline__ void split2(float v, __nv_bfloat16& hi, __nv_bfloat16& lo) {
    hi = __float2bfloat16(v);
    lo = __float2bfloat16(v - __bfloat162float(hi));
}

__device__ __forceinline__ void mma_bf16(float c[4], const unsigned int a[4], const unsigned int b[2]) {
    asm volatile(
        "mma.sync.aligned.m16n8k16.row.col.f32.bf16.bf16.f32 "
        "{%0,%1,%2,%3},{%4,%5,%6,%7},{%8,%9},{%0,%1,%2,%3};"
        : "+f"(c[0]), "+f"(c[1]), "+f"(c[2]), "+f"(c[3])
        : "r"(a[0]), "r"(a[1]), "r"(a[2]), "r"(a[3]), "r"(b[0]), "r"(b[1]));
}

__device__ __forceinline__ void ldsm_x4(unsigned int a[4], unsigned int addr) {
    asm volatile("ldmatrix.sync.aligned.m8n8.x4.shared.b16 {%0,%1,%2,%3}, [%4];"
                 : "=r"(a[0]), "=r"(a[1]), "=r"(a[2]), "=r"(a[3]) : "r"(addr));
}
__device__ __forceinline__ void ldsm_x2(unsigned int b[2], unsigned int addr) {
    asm volatile("ldmatrix.sync.aligned.m8n8.x2.shared.b16 {%0,%1}, [%2];"
                 : "=r"(b[0]), "=r"(b[1]) : "r"(addr));
}
__device__ __forceinline__ void cpa16(unsigned int dst, const void* src) {
    asm volatile("cp.async.cg.shared.global [%0], [%1], 16;" :: "r"(dst), "l"(src));
}

// ---- one-time prep kernels ----
// g_Wh/g_Wl[c][k]: col c' = j*4+q <-> original col q*H+j; k rows: [0,H)=Wh, [H,2H)=Wattn, [2H,..)=Wx
__global__ void reorder_kernel(const float* __restrict__ Wx, const float* __restrict__ Wh,
                               const float* __restrict__ Wattn, const float* __restrict__ b) {
    int k = blockIdx.x * blockDim.x + threadIdx.x;
    int c = blockIdx.y;
    if (k >= KT_) return;
    int oc = (c & 3) * H_ + (c >> 2);
    float w;
    if (k < H_)            w = Wh[k * C4_ + oc];
    else if (k < 2 * H_)   w = Wattn[(k - H_) * C4_ + oc];
    else                   w = Wx[(k - 2 * H_) * C4_ + oc];
    __nv_bfloat16 hi, lo;
    split2(w, hi, lo);
    g_Wh[(size_t)c * KT_ + k] = hi;
    g_Wl[(size_t)c * KT_ + k] = lo;
    if (k == 0 && blockIdx.x == 0) g_bv[c] = b[oc];
}

__global__ void xsplit_kernel(const float* __restrict__ x) {
    size_t i = (size_t)blockIdx.x * blockDim.x + threadIdx.x;
    size_t total = (size_t)N_ * T_ * D_;
    size_t stride = (size_t)gridDim.x * blockDim.x;
    for (; i < total; i += stride) {
        __nv_bfloat16 hi, lo;
        split2(x[i], hi, lo);
        g_xh[i] = hi;
        g_xl[i] = lo;
    }
}

__global__ void init_kernel(const float* __restrict__ A) {
    int i = blockIdx.x * blockDim.x + threadIdx.x;
    if (i < N_ * H_) {
        const float4* a = reinterpret_cast<const float4*>(A + (size_t)i * 16);
        float4 a0 = a[0], a1 = a[1], a2 = a[2], a3 = a[3];
        float s = a0.x + a0.y + a0.z + a0.w + a1.x + a1.y + a1.z + a1.w
                + a2.x + a2.y + a2.z + a2.w + a3.x + a3.y + a3.z + a3.w;
        s *= (1.0f / 16.0f);
        g_h[0][i] = s;
        g_c[i] = s;
        __nv_bfloat16 hi, lo;
        split2(s, hi, lo);
        g_zh[0][i] = hi;
        g_zl[0][i] = lo;
    }
}

// ---- per-step attention (single pass, A rows in regs, 512 threads) ----
__global__ __launch_bounds__(512) void attn_kernel(const float* __restrict__ A, int cur) {
    int n = blockIdx.x;
    int tid = threadIdx.x;
    const float* __restrict__ hn = g_h[cur] + n * H_;
    const float* __restrict__ An = A + (size_t)n * H_ * 16;

    float4 ar[2][4];
    float s[16];
#pragma unroll
    for (int l = 0; l < 16; l++) s[l] = 0.0f;
#pragma unroll
    for (int r = 0; r < 2; r++) {
        int hh = tid + r * 512;
        float hv = hn[hh];
        const float4* ap = reinterpret_cast<const float4*>(An + hh * 16);
#pragma unroll
        for (int v = 0; v < 4; v++) {
            float4 a = ap[v];
            ar[r][v] = a;
            s[v * 4 + 0] += a.x * hv;
            s[v * 4 + 1] += a.y * hv;
            s[v * 4 + 2] += a.z * hv;
            s[v * 4 + 3] += a.w * hv;
        }
    }
#pragma unroll
    for (int off = 16; off > 0; off >>= 1)
#pragma unroll
        for (int l = 0; l < 16; l++) s[l] += __shfl_xor_sync(0xffffffffu, s[l], off);

    __shared__ float red[16][16];
    int wid = tid >> 5, lane = tid & 31;
    if (lane == 0)
#pragma unroll
        for (int l = 0; l < 16; l++) red[wid][l] = s[l];
    __syncthreads();

    float w[16];
    float mx = -1e30f;
#pragma unroll
    for (int l = 0; l < 16; l++) {
        float t = 0.0f;
#pragma unroll
        for (int ww = 0; ww < 16; ww++) t += red[ww][l];
        w[l] = t * 0.03125f;   // 1/sqrt(1024)
        mx = fmaxf(mx, w[l]);
    }
    float sum = 0.0f;
#pragma unroll
    for (int l = 0; l < 16; l++) { w[l] = expf(w[l] - mx); sum += w[l]; }
    float inv = 1.0f / sum;
#pragma unroll
    for (int l = 0; l < 16; l++) w[l] *= inv;

#pragma unroll
    for (int r = 0; r < 2; r++) {
        int hh = tid + r * 512;
        float acc = 0.0f;
#pragma unroll
        for (int v = 0; v < 4; v++) {
            float4 a = ar[r][v];
            acc += a.x * w[v * 4 + 0] + a.y * w[v * 4 + 1]
                 + a.z * w[v * 4 + 2] + a.w * w[v * 4 + 3];
        }
        __nv_bfloat16 hi, lo;
        split2(acc, hi, lo);
        g_ah[n * H_ + hh] = hi;
        g_al[n * H_ + hh] = lo;
    }
}

// ---- fused step: [h|attn|x_t] @ W (bf16-split mma.sync, cp.async 4-stage, ldmatrix) + LSTM ----
__global__ __launch_bounds__(256) void step_kernel(float* __restrict__ out, int t, int cur) {
    extern __shared__ __align__(16) unsigned char sm[];
    const unsigned int smb = (unsigned int)__cvta_generic_to_shared(sm);

    const int tid = threadIdx.x;
    const int bn = blockIdx.x * 128;   // gate-interleaved column base
    const int bm = blockIdx.y * 64;    // batch-row base
    const int nxt = cur ^ 1;

    const int wid = tid >> 5, lane = tid & 31;
    const int wm = wid >> 2, wn = wid & 3;        // 2 x 4 warp grid
    const int cprow = tid >> 2, cpq = tid & 3;    // cp.async mapping

    float acc[2][4][4];
#pragma unroll
    for (int mt = 0; mt < 2; mt++)
#pragma unroll
        for (int nt = 0; nt < 4; nt++)
#pragma unroll
            for (int q = 0; q < 4; q++) acc[mt][nt][q] = 0.0f;

    const __nv_bfloat16* zh = g_zh[cur];
    const __nv_bfloat16* zl = g_zl[cur];

    // ---- stage issue helper (inlined via lambda) ----
    auto issue = [&](int tl) {
        int k0 = tl * KC;
        unsigned int base = smb + (tl % STAGES) * STAGE_BYTES;
        // A tile: 64 rows x 32 halves (hi + lo)
        int n = bm + cprow;
        const __nv_bfloat16 *sh, *sl;
        if (k0 < H_) {
            sh = zh + n * H_ + k0;  sl = zl + n * H_ + k0;
        } else if (k0 < 2 * H_) {
            sh = g_ah + n * H_ + (k0 - H_);  sl = g_al + n * H_ + (k0 - H_);
        } else {
            size_t o = ((size_t)n * T_ + t) * D_ + (k0 - 2 * H_);
            sh = g_xh + o;  sl = g_xl + o;
        }
        cpa16(base + cprow * (SA * 2) + cpq * 16, sh + cpq * 8);
        cpa16(base + 64 * SA * 2 + cprow * (SA * 2) + cpq * 16, sl + cpq * 8);
        // B tile: 128 cols x 32 halves (hi + lo)
#pragma unroll
        for (int i = 0; i < 2; i++) {
            int cl = i * 64 + cprow;
            const __nv_bfloat16* wsrc_h = g_Wh + (size_t)(bn + cl) * KT_ + k0 + cpq * 8;
            const __nv_bfloat16* wsrc_l = g_Wl + (size_t)(bn + cl) * KT_ + k0 + cpq * 8;
            cpa16(base + 2 * 64 * SA * 2 + cl * (SB * 2) + cpq * 16, wsrc_h);
            cpa16(base + 2 * 64 * SA * 2 + 128 * SB * 2 + cl * (SB * 2) + cpq * 16, wsrc_l);
        }
    };

    // prologue: fill STAGES-1 stages
#pragma unroll
    for (int s = 0; s < STAGES - 1; s++) {
        issue(s);
        asm volatile("cp.async.commit_group;");
    }

    // ldmatrix per-lane address components (byte offsets within stage)
    const int a_row_l = (lane & 15);
    const int a_k_l = (lane >> 4) << 3;
    const int b_col_l = (lane & 7);
    const int b_k_l = (lane & 8) ? 8 : 0;

    for (int tile = 0; tile < NTILES; tile++) {
        asm volatile("cp.async.wait_group %0;" :: "n"(STAGES - 2));
        __syncthreads();
        int pf = tile + STAGES - 1;
        if (pf < NTILES) issue(pf);
        asm volatile("cp.async.commit_group;");

        unsigned int base = smb + (tile % STAGES) * STAGE_BYTES;
        unsigned int baseAh = base;
        unsigned int baseAl = base + 64 * SA * 2;
        unsigned int baseBh = base + 2 * 64 * SA * 2;
        unsigned int baseBl = baseBh + 128 * SB * 2;

#pragma unroll
        for (int kb = 0; kb < KC; kb += 16) {
            unsigned int ah[2][4], al[2][4], bh[4][2], bl[4][2];
#pragma unroll
            for (int mt = 0; mt < 2; mt++) {
                int row = wm * 32 + mt * 16 + a_row_l;
                int kk = kb + a_k_l;
                ldsm_x4(ah[mt], baseAh + (row * SA + kk) * 2);
                ldsm_x4(al[mt], baseAl + (row * SA + kk) * 2);
            }
#pragma unroll
            for (int nt = 0; nt < 4; nt++) {
                int col = wn * 32 + nt * 8 + b_col_l;
                int kk = kb + b_k_l;
                ldsm_x2(bh[nt], baseBh + (col * SB + kk) * 2);
                ldsm_x2(bl[nt], baseBl + (col * SB + kk) * 2);
            }
            // 3 passes, dependency reuse distance = 8
#pragma unroll
            for (int mt = 0; mt < 2; mt++)
#pragma unroll
                for (int nt = 0; nt < 4; nt++)
                    mma_bf16(acc[mt][nt], ah[mt], bh[nt]);
#pragma unroll
            for (int mt = 0; mt < 2; mt++)
#pragma unroll
                for (int nt = 0; nt < 4; nt++)
                    mma_bf16(acc[mt][nt], ah[mt], bl[nt]);
#pragma unroll
            for (int mt = 0; mt < 2; mt++)
#pragma unroll
                for (int nt = 0; nt < 4; nt++)
                    mma_bf16(acc[mt][nt], al[mt], bh[nt]);
        }
    }

    // ---- epilogue: regroup gates via smem, fused LSTM pointwise ----
    asm volatile("cp.async.wait_group 0;");
    __syncthreads();
    float* Cs = (float*)sm;
    const int g = lane >> 2, tg = lane & 3;
#pragma unroll
    for (int mt = 0; mt < 2; mt++)
#pragma unroll
        for (int nt = 0; nt < 4; nt++) {
            int r0 = wm * 32 + mt * 16 + g;
            int col = wn * 32 + nt * 8 + tg * 2;
            Cs[r0 * CS + col]           = acc[mt][nt][0];
            Cs[r0 * CS + col + 1]       = acc[mt][nt][1];
            Cs[(r0 + 8) * CS + col]     = acc[mt][nt][2];
            Cs[(r0 + 8) * CS + col + 1] = acc[mt][nt][3];
        }
    __syncthreads();

#pragma unroll
    for (int i = 0; i < 8; i++) {
        int lin = tid + i * 256;
        int m = lin >> 5, jj = lin & 31;
        float4 gg = *(const float4*)&Cs[m * CS + jj * 4];
        float4 bb = *(const float4*)&g_bv[bn + jj * 4];
        int n = bm + m;
        int j = (bn >> 2) + jj;
        float gi = gg.x + bb.x;
        float gf = gg.y + bb.y;
        float go = gg.z + bb.z;
        float gq = gg.w + bb.w;
        float cold = g_c[n * H_ + j];
        float cn = sigf(gf) * cold + sigf(gi) * tanhf(gq);
        float hn = sigf(go) * tanhf(cn);
        g_c[n * H_ + j] = cn;
        g_h[nxt][n * H_ + j] = hn;
        __nv_bfloat16 hi, lo;
        split2(hn, hi, lo);
        g_zh[nxt][n * H_ + j] = hi;
        g_zl[nxt][n * H_ + j] = lo;
        out[((size_t)n * T_ + t) * H_ + j] = hn;
    }
}

extern "C" void kernel_launch(void* const* d_in, const int* in_sizes, int n_in,
                              void* d_out, int out_size) {
    (void)in_sizes; (void)n_in; (void)out_size;
    const float* x     = (const float*)d_in[0];
    const float* A     = (const float*)d_in[1];
    const float* Wx    = (const float*)d_in[2];
    const float* Wh    = (const float*)d_in[3];
    const float* Wattn = (const float*)d_in[4];
    const float* b     = (const float*)d_in[5];
    float* out = (float*)d_out;

    cudaFuncSetAttribute(step_kernel, cudaFuncAttributeMaxDynamicSharedMemorySize,
                         STAGES * STAGE_BYTES);

    reorder_kernel<<<dim3(KT_ / 256, C4_), 256>>>(Wx, Wh, Wattn, b);
    xsplit_kernel<<<2048, 256>>>(x);
    init_kernel<<<(N_ * H_ + 255) / 256, 256>>>(A);

    int cur = 0;
    for (int t = 0; t < T_; t++) {
        attn_kernel<<<N_, 512>>>(A, cur);
        step_kernel<<<dim3(C4_ / 128, N_ / 64), 256, STAGES * STAGE_BYTES>>>(out, t, cur);
        cur ^= 1;
    }
}